// round 1
// baseline (speedup 1.0000x reference)
#include <cuda_runtime.h>
#include <math.h>

#define Bn 4
#define T 1024
#define C 1024
#define H 16
#define HD 64
#define FF 4096
#define MROWS (Bn*T)   // 4096

// ---------------- scratch (device globals; no runtime allocation) ----------------
__device__ float g_wqkv[C * 3 * C];                       // packed [C, 3C] qkv weight
__device__ float g_xn[MROWS * C];                         // layernorm output (reused)
__device__ float g_qkv[(size_t)MROWS * 3 * C];            // [M, 3C] fused qkv
__device__ float g_scores[(size_t)Bn * H * T * T];        // [B,H,T,T] attention scores
__device__ float g_att[MROWS * C];                        // concat attention out [M,C]
__device__ float g_x1[MROWS * C];                         // x + attn_proj
__device__ float g_h[(size_t)MROWS * FF];                 // FFN hidden

// ---------------- layernorm: one block per row ----------------
__global__ void layernorm_k(const float* __restrict__ x, const float* __restrict__ g,
                            const float* __restrict__ b, float* __restrict__ out) {
    int row = blockIdx.x;
    const float* xr = x + (size_t)row * C;
    float* yr = out + (size_t)row * C;
    float s = 0.f, s2 = 0.f;
    for (int i = threadIdx.x; i < C; i += blockDim.x) {
        float v = xr[i]; s += v; s2 += v * v;
    }
    __shared__ float sh[64];
    int lid = threadIdx.x & 31, wid = threadIdx.x >> 5;
    #pragma unroll
    for (int o = 16; o > 0; o >>= 1) {
        s  += __shfl_xor_sync(0xffffffffu, s,  o);
        s2 += __shfl_xor_sync(0xffffffffu, s2, o);
    }
    if (lid == 0) { sh[wid] = s; sh[wid + 32] = s2; }
    __syncthreads();
    if (threadIdx.x == 0) {
        float a = 0.f, a2 = 0.f;
        int nw = blockDim.x >> 5;
        for (int w = 0; w < nw; w++) { a += sh[w]; a2 += sh[w + 32]; }
        sh[0] = a; sh[1] = a2;
    }
    __syncthreads();
    float mean = sh[0] * (1.0f / C);
    float var  = sh[1] * (1.0f / C) - mean * mean;
    float rstd = rsqrtf(var + 1e-5f);
    for (int i = threadIdx.x; i < C; i += blockDim.x)
        yr[i] = (xr[i] - mean) * rstd * g[i] + b[i];
}

// ---------------- pack Wq/Wk/Wv [H,C,HD] -> g_wqkv [C, 3C] ----------------
__global__ void pack_qkv_k(const float* __restrict__ Wq, const float* __restrict__ Wk,
                           const float* __restrict__ Wv) {
    int idx = blockIdx.x * blockDim.x + threadIdx.x;
    if (idx >= C * 3 * C) return;
    int n = idx % (3 * C);
    int k = idx / (3 * C);
    const float* W; int nn;
    if (n < C)          { W = Wq; nn = n; }
    else if (n < 2 * C) { W = Wk; nn = n - C; }
    else                { W = Wv; nn = n - 2 * C; }
    int h = nn >> 6, d = nn & 63;
    g_wqkv[idx] = W[((size_t)h * C + k) * HD + d];
}

// ---------------- SGEMM: Y[M,N] = A[M,K] @ B[K,N]; EPI: 0 none, 1 bias, 2 bias+gelu, 3 bias+resid
template <int EPI>
__global__ void sgemm_k(const float* __restrict__ A, const float* __restrict__ Bm,
                        float* __restrict__ Cm, int Mn, int Nn, int Kn,
                        const float* __restrict__ bias, const float* __restrict__ resid) {
    __shared__ float As[8][128];
    __shared__ float Bs[8][128];
    int bx = blockIdx.x;          // N tile
    int by = blockIdx.y;          // M tile
    int tid = threadIdx.x;
    int tr = tid >> 4, tc = tid & 15;     // 16x16 threads, 8x8 each
    float acc[8][8];
    #pragma unroll
    for (int i = 0; i < 8; i++)
        #pragma unroll
        for (int j = 0; j < 8; j++) acc[i][j] = 0.f;

    int arow = tid >> 1, acol = (tid & 1) * 4;     // A: 128 rows x 8 cols
    int brow = tid >> 5, bcol = (tid & 31) * 4;    // B: 8 rows x 128 cols
    const float* Ab = A + (size_t)(by * 128) * Kn;
    const float* Bb = Bm + bx * 128;

    for (int k0 = 0; k0 < Kn; k0 += 8) {
        float4 av = *(const float4*)(Ab + (size_t)arow * Kn + k0 + acol);
        As[acol + 0][arow] = av.x;
        As[acol + 1][arow] = av.y;
        As[acol + 2][arow] = av.z;
        As[acol + 3][arow] = av.w;
        float4 bv = *(const float4*)(Bb + (size_t)(k0 + brow) * Nn + bcol);
        *(float4*)&Bs[brow][bcol] = bv;
        __syncthreads();
        #pragma unroll
        for (int k = 0; k < 8; k++) {
            float ra[8], rb[8];
            *(float4*)&ra[0] = *(const float4*)&As[k][tr * 8];
            *(float4*)&ra[4] = *(const float4*)&As[k][tr * 8 + 4];
            *(float4*)&rb[0] = *(const float4*)&Bs[k][tc * 8];
            *(float4*)&rb[4] = *(const float4*)&Bs[k][tc * 8 + 4];
            #pragma unroll
            for (int i = 0; i < 8; i++)
                #pragma unroll
                for (int j = 0; j < 8; j++)
                    acc[i][j] = fmaf(ra[i], rb[j], acc[i][j]);
        }
        __syncthreads();
    }

    #pragma unroll
    for (int i = 0; i < 8; i++) {
        int r = by * 128 + tr * 8 + i;
        #pragma unroll
        for (int j = 0; j < 8; j += 4) {
            int c = bx * 128 + tc * 8 + j;
            float v[4] = {acc[i][j], acc[i][j + 1], acc[i][j + 2], acc[i][j + 3]};
            if (EPI >= 1) {
                #pragma unroll
                for (int t = 0; t < 4; t++) v[t] += bias[c + t];
            }
            if (EPI == 2) {
                #pragma unroll
                for (int t = 0; t < 4; t++)
                    v[t] = 0.5f * v[t] * (1.0f + erff(v[t] * 0.70710678118654752440f));
            }
            if (EPI == 3) {
                float4 rr = *(const float4*)(resid + (size_t)r * Nn + c);
                v[0] += rr.x; v[1] += rr.y; v[2] += rr.z; v[3] += rr.w;
            }
            float4 o = make_float4(v[0], v[1], v[2], v[3]);
            *(float4*)(Cm + (size_t)r * Nn + c) = o;
        }
    }
}

// ---------------- scores: S[b,h,tq,tk] = scale * q . k  (only lower-triangle tiles) ----------------
__global__ void scores_k(const float* __restrict__ qkv) {
    int bh = blockIdx.z;
    int b = bh >> 4, h = bh & 15;
    int qt = blockIdx.y, kt = blockIdx.x;
    if (kt > qt) return;
    __shared__ float Qs[64][65];
    __shared__ float Ks[64][65];
    const float* qbase = qkv + ((size_t)(b * T) + qt * 64) * 3072 + h * 64;
    const float* kbase = qkv + ((size_t)(b * T) + kt * 64) * 3072 + 1024 + h * 64;
    for (int i = threadIdx.x; i < 64 * 64; i += 256) {
        int r = i >> 6, c = i & 63;
        Qs[r][c] = qbase[(size_t)r * 3072 + c];
        Ks[r][c] = kbase[(size_t)r * 3072 + c];
    }
    __syncthreads();
    int tr = threadIdx.x >> 4, tc = threadIdx.x & 15;
    float acc[4][4];
    #pragma unroll
    for (int i = 0; i < 4; i++)
        #pragma unroll
        for (int j = 0; j < 4; j++) acc[i][j] = 0.f;
    #pragma unroll 8
    for (int k = 0; k < 64; k++) {
        float ra[4], rb[4];
        #pragma unroll
        for (int i = 0; i < 4; i++) ra[i] = Qs[tr * 4 + i][k];
        #pragma unroll
        for (int j = 0; j < 4; j++) rb[j] = Ks[tc * 4 + j][k];
        #pragma unroll
        for (int i = 0; i < 4; i++)
            #pragma unroll
            for (int j = 0; j < 4; j++)
                acc[i][j] = fmaf(ra[i], rb[j], acc[i][j]);
    }
    const float scale = 0.125f;  // HD^-0.5
    float* S = g_scores + ((size_t)bh * T + qt * 64) * T + kt * 64;
    #pragma unroll
    for (int i = 0; i < 4; i++)
        #pragma unroll
        for (int j = 0; j < 4; j++)
            S[(size_t)(tr * 4 + i) * T + tc * 4 + j] = acc[i][j] * scale;
}

// ---------------- causal softmax: one block per (b,h,tq) row ----------------
__global__ void softmax_k() {
    size_t row = blockIdx.x;
    int tq = (int)(row % T);
    float* S = g_scores + row * (size_t)T;
    int n = tq + 1;
    __shared__ float sh[8];
    int tid = threadIdx.x, lid = tid & 31, wid = tid >> 5;

    float mx = -3.4e38f;
    for (int i = tid; i < n; i += 256) mx = fmaxf(mx, S[i]);
    #pragma unroll
    for (int o = 16; o > 0; o >>= 1) mx = fmaxf(mx, __shfl_xor_sync(0xffffffffu, mx, o));
    if (lid == 0) sh[wid] = mx;
    __syncthreads();
    if (tid == 0) {
        float m = sh[0];
        for (int w = 1; w < 8; w++) m = fmaxf(m, sh[w]);
        sh[0] = m;
    }
    __syncthreads();
    mx = sh[0];
    __syncthreads();

    float sum = 0.f;
    for (int i = tid; i < n; i += 256) {
        float e = expf(S[i] - mx);
        S[i] = e;
        sum += e;
    }
    #pragma unroll
    for (int o = 16; o > 0; o >>= 1) sum += __shfl_xor_sync(0xffffffffu, sum, o);
    if (lid == 0) sh[wid] = sum;
    __syncthreads();
    if (tid == 0) {
        float s = 0.f;
        for (int w = 0; w < 8; w++) s += sh[w];
        sh[0] = s;
    }
    __syncthreads();
    float inv = 1.0f / sh[0];
    for (int i = tid; i < n; i += 256) S[i] *= inv;
    for (int i = n + tid; i < T; i += 256) S[i] = 0.f;
}

// ---------------- AV: O[b,tq, h*64+d] = sum_tk P[b,h,tq,tk] * V[b,h,tk,d] ----------------
__global__ void av_k(const float* __restrict__ qkv, float* __restrict__ att) {
    int bh = blockIdx.z;
    int b = bh >> 4, h = bh & 15;
    int qt = blockIdx.x;
    __shared__ float Ps[64][33];
    __shared__ float Vs[32][65];
    int tid = threadIdx.x;
    int tr = tid >> 4, tc = tid & 15;
    float acc[4][4];
    #pragma unroll
    for (int i = 0; i < 4; i++)
        #pragma unroll
        for (int j = 0; j < 4; j++) acc[i][j] = 0.f;

    const float* Sbase = g_scores + ((size_t)bh * T + qt * 64) * T;
    const float* Vbase = qkv + 2048 + h * 64;
    int kmax = (qt + 1) * 64;   // P is 0 beyond the diagonal
    for (int k0 = 0; k0 < kmax; k0 += 32) {
        for (int i = tid; i < 2048; i += 256) {
            int r = i >> 5, c = i & 31;
            Ps[r][c] = Sbase[(size_t)r * T + k0 + c];
        }
        for (int i = tid; i < 2048; i += 256) {
            int r = i >> 6, c = i & 63;
            Vs[r][c] = Vbase[(size_t)(b * T + k0 + r) * 3072 + c];
        }
        __syncthreads();
        #pragma unroll 8
        for (int k = 0; k < 32; k++) {
            float ra[4], rb[4];
            #pragma unroll
            for (int i = 0; i < 4; i++) ra[i] = Ps[tr * 4 + i][k];
            #pragma unroll
            for (int j = 0; j < 4; j++) rb[j] = Vs[k][tc * 4 + j];
            #pragma unroll
            for (int i = 0; i < 4; i++)
                #pragma unroll
                for (int j = 0; j < 4; j++)
                    acc[i][j] = fmaf(ra[i], rb[j], acc[i][j]);
        }
        __syncthreads();
    }
    size_t obase = ((size_t)b * T + qt * 64) * 1024 + h * 64;
    #pragma unroll
    for (int i = 0; i < 4; i++)
        #pragma unroll
        for (int j = 0; j < 4; j++)
            att[obase + (size_t)(tr * 4 + i) * 1024 + tc * 4 + j] = acc[i][j];
}

// ---------------- launch ----------------
extern "C" void kernel_launch(void* const* d_in, const int* in_sizes, int n_in,
                              void* d_out, int out_size) {
    const float* x      = (const float*)d_in[0];
    const float* ln1_g  = (const float*)d_in[1];
    const float* ln1_b  = (const float*)d_in[2];
    const float* ln2_g  = (const float*)d_in[3];
    const float* ln2_b  = (const float*)d_in[4];
    const float* Wq     = (const float*)d_in[5];
    const float* Wk     = (const float*)d_in[6];
    const float* Wv     = (const float*)d_in[7];
    const float* Wproj  = (const float*)d_in[8];
    const float* bproj  = (const float*)d_in[9];
    const float* W1     = (const float*)d_in[10];
    const float* b1     = (const float*)d_in[11];
    const float* W2     = (const float*)d_in[12];
    const float* b2     = (const float*)d_in[13];
    float* out = (float*)d_out;

    float *p_wqkv, *p_xn, *p_qkv, *p_att, *p_x1, *p_h;
    cudaGetSymbolAddress((void**)&p_wqkv, g_wqkv);
    cudaGetSymbolAddress((void**)&p_xn,   g_xn);
    cudaGetSymbolAddress((void**)&p_qkv,  g_qkv);
    cudaGetSymbolAddress((void**)&p_att,  g_att);
    cudaGetSymbolAddress((void**)&p_x1,   g_x1);
    cudaGetSymbolAddress((void**)&p_h,    g_h);

    // 1) LN1
    layernorm_k<<<MROWS, 256>>>(x, ln1_g, ln1_b, p_xn);
    // 2) pack qkv weights
    pack_qkv_k<<<(C * 3 * C + 255) / 256, 256>>>(Wq, Wk, Wv);
    // 3) fused QKV GEMM: [4096,1024] @ [1024,3072]
    sgemm_k<0><<<dim3(3 * C / 128, MROWS / 128), 256>>>(p_xn, p_wqkv, p_qkv,
                                                        MROWS, 3 * C, C, nullptr, nullptr);
    // 4) causal scores (lower-triangle tiles only)
    scores_k<<<dim3(T / 64, T / 64, Bn * H), 256>>>(p_qkv);
    // 5) causal softmax
    softmax_k<<<Bn * H * T, 256>>>();
    // 6) P @ V -> concat att [M, C]
    av_k<<<dim3(T / 64, 1, Bn * H), 256>>>(p_qkv, p_att);
    // 7) proj + bias + residual(x) -> x1
    sgemm_k<3><<<dim3(C / 128, MROWS / 128), 256>>>(p_att, Wproj, p_x1,
                                                    MROWS, C, C, bproj, x);
    // 8) LN2
    layernorm_k<<<MROWS, 256>>>(p_x1, ln2_g, ln2_b, p_xn);
    // 9) FFN1 + bias + exact GELU
    sgemm_k<2><<<dim3(FF / 128, MROWS / 128), 256>>>(p_xn, W1, p_h,
                                                     MROWS, FF, C, b1, nullptr);
    // 10) FFN2 + bias + residual(x1) -> out
    sgemm_k<3><<<dim3(C / 128, MROWS / 128), 256>>>(p_h, W2, out,
                                                    MROWS, C, FF, b2, p_x1);
}

// round 3
// speedup vs baseline: 2.1687x; 2.1687x over previous
#include <cuda_runtime.h>
#include <math.h>
#include <stdint.h>

#define Bn 4
#define T 1024
#define C 1024
#define H 16
#define HD 64
#define FF 4096
#define MROWS (Bn*T)   // 4096

// ---------------- scratch (device globals; no runtime allocation) ----------------
__device__ __align__(1024) float g_wqkvT[3*C * C];               // [3072,1024] W_qkv^T (tf32)
__device__ __align__(1024) float g_wprojT[C * C];                // [1024,1024] Wproj^T
__device__ __align__(1024) float g_w1T[FF * C];                  // [4096,1024] W1^T
__device__ __align__(1024) float g_w2T[C * FF];                  // [1024,4096] W2^T
__device__ __align__(1024) float g_xn[MROWS * C];                // layernorm output (tf32)
__device__ __align__(1024) float g_qkv[(size_t)MROWS * 3 * C];   // [M, 3C]
__device__ __align__(1024) float g_scores[(size_t)Bn * H * T * T];
__device__ __align__(1024) float g_att[MROWS * C];               // attention out (tf32)
__device__ __align__(1024) float g_x1[MROWS * C];                // x + attn_proj
__device__ __align__(1024) float g_h[(size_t)MROWS * FF];        // FFN hidden (tf32)

// ---------------- helpers ----------------
__device__ __forceinline__ uint32_t smem_u32(const void* p) {
    uint32_t a;
    asm("{ .reg .u64 t; cvta.to.shared.u64 t, %1; cvt.u32.u64 %0, t; }" : "=r"(a) : "l"(p));
    return a;
}
__device__ __forceinline__ float to_tf32(float x) {
    float r; asm("cvt.rna.tf32.f32 %0, %1;" : "=f"(r) : "f"(x)); return r;
}

#define CP_ASYNC16(dst, src) \
    asm volatile("cp.async.cg.shared.global [%0], [%1], 16;" :: "r"(dst), "l"(src) : "memory")
#define CP_COMMIT() asm volatile("cp.async.commit_group;" ::: "memory")
#define CP_WAIT(n)  asm volatile("cp.async.wait_group %0;" :: "n"(n) : "memory")

__device__ __forceinline__ void mma_tf32(float* d, const uint32_t* a, const uint32_t* b) {
    asm volatile(
        "mma.sync.aligned.m16n8k8.row.col.f32.tf32.tf32.f32 "
        "{%0,%1,%2,%3}, {%4,%5,%6,%7}, {%8,%9}, {%0,%1,%2,%3};"
        : "+f"(d[0]), "+f"(d[1]), "+f"(d[2]), "+f"(d[3])
        : "r"(a[0]), "r"(a[1]), "r"(a[2]), "r"(a[3]), "r"(b[0]), "r"(b[1]));
}

// ---------------- tensor-core GEMM: C[M,N] = A[M,K] @ B[N,K]^T (both row-major, tf32) ----
// 128x128x32 tile, 8 warps (warp tile 64x32), 3-stage cp.async pipeline.
// EPI: 0 none, 2 bias+gelu(+tf32 round), 3 bias+resid
#define BK 32
#define PADK 36                        // padded k-stride (floats): (4*row+k)%32 conflict-free
#define STG 3
#define TILE_F (128 * PADK)            // floats per tile per stage
#define GEMM_SMEM (STG * 2 * TILE_F * 4)

template <int EPI>
__global__ __launch_bounds__(256, 1) void gemm_mma(
    const float* __restrict__ Ag, const float* __restrict__ Bg, float* __restrict__ Cm,
    int Kn, int Nn,
    const float* __restrict__ bias, const float* __restrict__ resid)
{
    extern __shared__ float sm[];
    float* smA = sm;                       // [STG][128][PADK]
    float* smB = sm + STG * TILE_F;        // [STG][128][PADK]
    int tid = threadIdx.x, lane = tid & 31, wid = tid >> 5;
    int bx = blockIdx.x, by = blockIdx.y;
    int wm = (wid >> 2) * 64, wn = (wid & 3) * 32;

    const int NT = Kn >> 5;                // k-tiles of 32

    // per-thread cp.async source/dest precompute: 4 chunks for A, 4 for B
    int row0 = tid >> 1;                   // chunk = tid + i*256 -> row = chunk>>3
    // chunk i: chunk = tid + i*256; row = chunk>>3 = (tid>>3) + i*32; c16 = tid&7
    int crow = tid >> 3, ccol = (tid & 7) * 4;

    auto issue = [&](int s, int kt) {
        const float* As = Ag + ((size_t)(by * 128)) * Kn + kt * 32;
        const float* Bs = Bg + ((size_t)(bx * 128)) * Kn + kt * 32;
        uint32_t dA = smem_u32(smA + s * TILE_F);
        uint32_t dB = smem_u32(smB + s * TILE_F);
        #pragma unroll
        for (int i = 0; i < 4; i++) {
            int r = crow + i * 32;
            CP_ASYNC16(dA + (r * PADK + ccol) * 4, As + (size_t)r * Kn + ccol);
            CP_ASYNC16(dB + (r * PADK + ccol) * 4, Bs + (size_t)r * Kn + ccol);
        }
    };
    (void)row0;

    float acc[4][4][4];
    #pragma unroll
    for (int mi = 0; mi < 4; mi++)
        #pragma unroll
        for (int ni = 0; ni < 4; ni++)
            #pragma unroll
            for (int q = 0; q < 4; q++) acc[mi][ni][q] = 0.f;

    // prologue: stages 0..STG-2
    #pragma unroll
    for (int s = 0; s < STG - 1; s++) { issue(s, s); CP_COMMIT(); }

    int lq = lane >> 2, lr = lane & 3;

    for (int kt = 0; kt < NT; kt++) {
        int nx = kt + STG - 1;
        if (nx < NT) issue(nx % STG, nx);
        CP_COMMIT();
        CP_WAIT(STG - 2);
        __syncthreads();

        const float* At = smA + (kt % STG) * TILE_F;
        const float* Bt = smB + (kt % STG) * TILE_F;

        #pragma unroll
        for (int ks = 0; ks < 4; ks++) {
            int k0 = ks * 8;
            uint32_t a[4][4], b[4][2];
            #pragma unroll
            for (int mi = 0; mi < 4; mi++) {
                int r = wm + mi * 16 + lq;
                a[mi][0] = __float_as_uint(At[r * PADK + k0 + lr]);
                a[mi][1] = __float_as_uint(At[(r + 8) * PADK + k0 + lr]);
                a[mi][2] = __float_as_uint(At[r * PADK + k0 + lr + 4]);
                a[mi][3] = __float_as_uint(At[(r + 8) * PADK + k0 + lr + 4]);
            }
            #pragma unroll
            for (int ni = 0; ni < 4; ni++) {
                int n = wn + ni * 8 + lq;
                b[ni][0] = __float_as_uint(Bt[n * PADK + k0 + lr]);
                b[ni][1] = __float_as_uint(Bt[n * PADK + k0 + lr + 4]);
            }
            #pragma unroll
            for (int mi = 0; mi < 4; mi++)
                #pragma unroll
                for (int ni = 0; ni < 4; ni++)
                    mma_tf32(acc[mi][ni], a[mi], b[ni]);
        }
        __syncthreads();
    }

    // epilogue
    #pragma unroll
    for (int ni = 0; ni < 4; ni++) {
        int c = bx * 128 + wn + ni * 8 + lr * 2;
        float b0 = 0.f, b1 = 0.f;
        if (EPI >= 1) { b0 = bias[c]; b1 = bias[c + 1]; }
        #pragma unroll
        for (int mi = 0; mi < 4; mi++) {
            int r0 = by * 128 + wm + mi * 16 + lq;
            #pragma unroll
            for (int half = 0; half < 2; half++) {
                int r = r0 + half * 8;
                float v0 = acc[mi][ni][half * 2 + 0] + b0;
                float v1 = acc[mi][ni][half * 2 + 1] + b1;
                if (EPI == 2) {
                    v0 = to_tf32(0.5f * v0 * (1.0f + erff(v0 * 0.70710678118654752440f)));
                    v1 = to_tf32(0.5f * v1 * (1.0f + erff(v1 * 0.70710678118654752440f)));
                }
                if (EPI == 3) {
                    float2 rr = *(const float2*)(resid + (size_t)r * Nn + c);
                    v0 += rr.x; v1 += rr.y;
                }
                *(float2*)(Cm + (size_t)r * Nn + c) = make_float2(v0, v1);
            }
        }
    }
}

// ---------------- layernorm: one block per row, tf32-rounded output ----------------
__global__ void layernorm_k(const float* __restrict__ x, const float* __restrict__ g,
                            const float* __restrict__ b, float* __restrict__ out) {
    int row = blockIdx.x;
    const float* xr = x + (size_t)row * C;
    float* yr = out + (size_t)row * C;
    float s = 0.f, s2 = 0.f;
    for (int i = threadIdx.x; i < C; i += blockDim.x) {
        float v = xr[i]; s += v; s2 += v * v;
    }
    __shared__ float sh[64];
    int lid = threadIdx.x & 31, wid = threadIdx.x >> 5;
    #pragma unroll
    for (int o = 16; o > 0; o >>= 1) {
        s  += __shfl_xor_sync(0xffffffffu, s,  o);
        s2 += __shfl_xor_sync(0xffffffffu, s2, o);
    }
    if (lid == 0) { sh[wid] = s; sh[wid + 32] = s2; }
    __syncthreads();
    if (threadIdx.x == 0) {
        float a = 0.f, a2 = 0.f;
        int nw = blockDim.x >> 5;
        for (int w = 0; w < nw; w++) { a += sh[w]; a2 += sh[w + 32]; }
        sh[0] = a; sh[1] = a2;
    }
    __syncthreads();
    float mean = sh[0] * (1.0f / C);
    float var  = sh[1] * (1.0f / C) - mean * mean;
    float rstd = rsqrtf(var + 1e-5f);
    for (int i = threadIdx.x; i < C; i += blockDim.x)
        yr[i] = to_tf32((xr[i] - mean) * rstd * g[i] + b[i]);
}

// ---------------- pack Wq/Wk/Wv [H,C,HD] -> g_wqkvT [3C, C] (tf32) ----------------
__global__ void pack_qkv_k(const float* __restrict__ Wq, const float* __restrict__ Wk,
                           const float* __restrict__ Wv) {
    int idx = blockIdx.x * blockDim.x + threadIdx.x;
    if (idx >= C * 3 * C) return;
    int k = idx % C;
    int n = idx / C;
    const float* W; int nn;
    if (n < C)          { W = Wq; nn = n; }
    else if (n < 2 * C) { W = Wk; nn = n - C; }
    else                { W = Wv; nn = n - 2 * C; }
    int h = nn >> 6, d = nn & 63;
    g_wqkvT[idx] = to_tf32(W[((size_t)h * C + k) * HD + d]);
}

// ---------------- tiled transpose src[K,N] -> dst[N,K] (tf32) ----------------
__global__ void transpose_tf32(const float* __restrict__ src, float* __restrict__ dst,
                               int Kn, int Nn) {
    __shared__ float tile[32][33];
    int k0 = blockIdx.y * 32, n0 = blockIdx.x * 32;
    int tx = threadIdx.x, ty = threadIdx.y;
    #pragma unroll
    for (int r = ty; r < 32; r += 8)
        tile[r][tx] = src[(size_t)(k0 + r) * Nn + n0 + tx];
    __syncthreads();
    #pragma unroll
    for (int r = ty; r < 32; r += 8)
        dst[(size_t)(n0 + r) * Kn + k0 + tx] = to_tf32(tile[tx][r]);
}

// ---------------- scores: S[b,h,tq,tk] = scale * q . k  (lower-triangle tiles) ----------------
__global__ void scores_k(const float* __restrict__ qkv) {
    int bh = blockIdx.z;
    int b = bh >> 4, h = bh & 15;
    int qt = blockIdx.y, kt = blockIdx.x;
    if (kt > qt) return;
    __shared__ float Qs[64][65];
    __shared__ float Ks[64][65];
    const float* qbase = qkv + ((size_t)(b * T) + qt * 64) * 3072 + h * 64;
    const float* kbase = qkv + ((size_t)(b * T) + kt * 64) * 3072 + 1024 + h * 64;
    for (int i = threadIdx.x; i < 64 * 64; i += 256) {
        int r = i >> 6, c = i & 63;
        Qs[r][c] = qbase[(size_t)r * 3072 + c];
        Ks[r][c] = kbase[(size_t)r * 3072 + c];
    }
    __syncthreads();
    int tr = threadIdx.x >> 4, tc = threadIdx.x & 15;
    float acc[4][4];
    #pragma unroll
    for (int i = 0; i < 4; i++)
        #pragma unroll
        for (int j = 0; j < 4; j++) acc[i][j] = 0.f;
    #pragma unroll 8
    for (int k = 0; k < 64; k++) {
        float ra[4], rb[4];
        #pragma unroll
        for (int i = 0; i < 4; i++) ra[i] = Qs[tr * 4 + i][k];
        #pragma unroll
        for (int j = 0; j < 4; j++) rb[j] = Ks[tc * 4 + j][k];
        #pragma unroll
        for (int i = 0; i < 4; i++)
            #pragma unroll
            for (int j = 0; j < 4; j++)
                acc[i][j] = fmaf(ra[i], rb[j], acc[i][j]);
    }
    const float scale = 0.125f;
    float* S = g_scores + ((size_t)bh * T + qt * 64) * T + kt * 64;
    #pragma unroll
    for (int i = 0; i < 4; i++)
        #pragma unroll
        for (int j = 0; j < 4; j++)
            S[(size_t)(tr * 4 + i) * T + tc * 4 + j] = acc[i][j] * scale;
}

// ---------------- causal softmax: one block per (b,h,tq) row ----------------
__global__ void softmax_k() {
    size_t row = blockIdx.x;
    int tq = (int)(row % T);
    float* S = g_scores + row * (size_t)T;
    int n = tq + 1;
    __shared__ float sh[8];
    int tid = threadIdx.x, lid = tid & 31, wid = tid >> 5;

    float mx = -3.4e38f;
    for (int i = tid; i < n; i += 256) mx = fmaxf(mx, S[i]);
    #pragma unroll
    for (int o = 16; o > 0; o >>= 1) mx = fmaxf(mx, __shfl_xor_sync(0xffffffffu, mx, o));
    if (lid == 0) sh[wid] = mx;
    __syncthreads();
    if (tid == 0) {
        float m = sh[0];
        for (int w = 1; w < 8; w++) m = fmaxf(m, sh[w]);
        sh[0] = m;
    }
    __syncthreads();
    mx = sh[0];
    __syncthreads();

    float sum = 0.f;
    for (int i = tid; i < n; i += 256) {
        float e = expf(S[i] - mx);
        S[i] = e;
        sum += e;
    }
    #pragma unroll
    for (int o = 16; o > 0; o >>= 1) sum += __shfl_xor_sync(0xffffffffu, sum, o);
    if (lid == 0) sh[wid] = sum;
    __syncthreads();
    if (tid == 0) {
        float s = 0.f;
        for (int w = 0; w < 8; w++) s += sh[w];
        sh[0] = s;
    }
    __syncthreads();
    float inv = 1.0f / sh[0];
    for (int i = tid; i < n; i += 256) S[i] *= inv;
    for (int i = n + tid; i < T; i += 256) S[i] = 0.f;
}

// ---------------- AV: O[b,tq, h*64+d] = sum_tk P * V (tf32-rounded store) ----------------
__global__ void av_k(const float* __restrict__ qkv, float* __restrict__ att) {
    int bh = blockIdx.z;
    int b = bh >> 4, h = bh & 15;
    int qt = blockIdx.x;
    __shared__ float Ps[64][33];
    __shared__ float Vs[32][65];
    int tid = threadIdx.x;
    int tr = tid >> 4, tc = tid & 15;
    float acc[4][4];
    #pragma unroll
    for (int i = 0; i < 4; i++)
        #pragma unroll
        for (int j = 0; j < 4; j++) acc[i][j] = 0.f;

    const float* Sbase = g_scores + ((size_t)bh * T + qt * 64) * T;
    const float* Vbase = qkv + 2048 + h * 64;
    int kmax = (qt + 1) * 64;
    for (int k0 = 0; k0 < kmax; k0 += 32) {
        for (int i = tid; i < 2048; i += 256) {
            int r = i >> 5, c = i & 31;
            Ps[r][c] = Sbase[(size_t)r * T + k0 + c];
        }
        for (int i = tid; i < 2048; i += 256) {
            int r = i >> 6, c = i & 63;
            Vs[r][c] = Vbase[(size_t)(b * T + k0 + r) * 3072 + c];
        }
        __syncthreads();
        #pragma unroll 8
        for (int k = 0; k < 32; k++) {
            float ra[4], rb[4];
            #pragma unroll
            for (int i = 0; i < 4; i++) ra[i] = Ps[tr * 4 + i][k];
            #pragma unroll
            for (int j = 0; j < 4; j++) rb[j] = Vs[k][tc * 4 + j];
            #pragma unroll
            for (int i = 0; i < 4; i++)
                #pragma unroll
                for (int j = 0; j < 4; j++)
                    acc[i][j] = fmaf(ra[i], rb[j], acc[i][j]);
        }
        __syncthreads();
    }
    size_t obase = ((size_t)b * T + qt * 64) * 1024 + h * 64;
    #pragma unroll
    for (int i = 0; i < 4; i++)
        #pragma unroll
        for (int j = 0; j < 4; j++)
            att[obase + (size_t)(tr * 4 + i) * 1024 + tc * 4 + j] = to_tf32(acc[i][j]);
}

// ---------------- launch ----------------
extern "C" void kernel_launch(void* const* d_in, const int* in_sizes, int n_in,
                              void* d_out, int out_size) {
    const float* x      = (const float*)d_in[0];
    const float* ln1_g  = (const float*)d_in[1];
    const float* ln1_b  = (const float*)d_in[2];
    const float* ln2_g  = (const float*)d_in[3];
    const float* ln2_b  = (const float*)d_in[4];
    const float* Wq     = (const float*)d_in[5];
    const float* Wk     = (const float*)d_in[6];
    const float* Wv     = (const float*)d_in[7];
    const float* Wproj  = (const float*)d_in[8];
    const float* bproj  = (const float*)d_in[9];
    const float* W1     = (const float*)d_in[10];
    const float* b1     = (const float*)d_in[11];
    const float* W2     = (const float*)d_in[12];
    const float* b2     = (const float*)d_in[13];
    float* out = (float*)d_out;

    float *p_wqkvT, *p_wprojT, *p_w1T, *p_w2T, *p_xn, *p_qkv, *p_att, *p_x1, *p_h;
    cudaGetSymbolAddress((void**)&p_wqkvT,  g_wqkvT);
    cudaGetSymbolAddress((void**)&p_wprojT, g_wprojT);
    cudaGetSymbolAddress((void**)&p_w1T,    g_w1T);
    cudaGetSymbolAddress((void**)&p_w2T,    g_w2T);
    cudaGetSymbolAddress((void**)&p_xn,     g_xn);
    cudaGetSymbolAddress((void**)&p_qkv,    g_qkv);
    cudaGetSymbolAddress((void**)&p_att,    g_att);
    cudaGetSymbolAddress((void**)&p_x1,     g_x1);
    cudaGetSymbolAddress((void**)&p_h,      g_h);

    cudaFuncSetAttribute(gemm_mma<0>, cudaFuncAttributeMaxDynamicSharedMemorySize, GEMM_SMEM);
    cudaFuncSetAttribute(gemm_mma<2>, cudaFuncAttributeMaxDynamicSharedMemorySize, GEMM_SMEM);
    cudaFuncSetAttribute(gemm_mma<3>, cudaFuncAttributeMaxDynamicSharedMemorySize, GEMM_SMEM);

    // 1) LN1 -> xn (tf32)
    layernorm_k<<<MROWS, 256>>>(x, ln1_g, ln1_b, p_xn);
    // 2) weight packs / transposes (tf32)
    pack_qkv_k<<<(C * 3 * C + 255) / 256, 256>>>(Wq, Wk, Wv);
    transpose_tf32<<<dim3(C / 32, C / 32),  dim3(32, 8)>>>(Wproj, p_wprojT, C, C);
    transpose_tf32<<<dim3(FF / 32, C / 32), dim3(32, 8)>>>(W1, p_w1T, C, FF);
    transpose_tf32<<<dim3(C / 32, FF / 32), dim3(32, 8)>>>(W2, p_w2T, FF, C);
    // 3) QKV GEMM (tensor): [4096,1024] @ [1024,3072]
    gemm_mma<0><<<dim3(3 * C / 128, MROWS / 128), 256, GEMM_SMEM>>>(
        p_xn, p_wqkvT, p_qkv, C, 3 * C, nullptr, nullptr);
    // 4) attention (SIMT)
    scores_k<<<dim3(T / 64, T / 64, Bn * H), 256>>>(p_qkv);
    softmax_k<<<Bn * H * T, 256>>>();
    av_k<<<dim3(T / 64, 1, Bn * H), 256>>>(p_qkv, p_att);
    // 5) proj + bias + residual(x) -> x1
    gemm_mma<3><<<dim3(C / 128, MROWS / 128), 256, GEMM_SMEM>>>(
        p_att, p_wprojT, p_x1, C, C, bproj, x);
    // 6) LN2 -> xn (tf32)
    layernorm_k<<<MROWS, 256>>>(p_x1, ln2_g, ln2_b, p_xn);
    // 7) FFN1 + bias + gelu -> h (tf32)
    gemm_mma<2><<<dim3(FF / 128, MROWS / 128), 256, GEMM_SMEM>>>(
        p_xn, p_w1T, p_h, C, FF, b1, nullptr);
    // 8) FFN2 + bias + residual(x1) -> out
    gemm_mma<3><<<dim3(C / 128, MROWS / 128), 256, GEMM_SMEM>>>(
        p_h, p_w2T, out, FF, C, b2, p_x1);
}

// round 4
// speedup vs baseline: 3.1448x; 1.4501x over previous
#include <cuda_runtime.h>
#include <math.h>
#include <stdint.h>

#define Bn 4
#define T 1024
#define C 1024
#define H 16
#define HD 64
#define FF 4096
#define MROWS (Bn*T)   // 4096

// ---------------- scratch (device globals; no runtime allocation) ----------------
__device__ __align__(1024) float g_wqkvT[3*C * C];               // [3072,1024] W_qkv^T (tf32)
__device__ __align__(1024) float g_wprojT[C * C];                // [1024,1024] Wproj^T
__device__ __align__(1024) float g_w1T[FF * C];                  // [4096,1024] W1^T
__device__ __align__(1024) float g_w2T[C * FF];                  // [1024,4096] W2^T
__device__ __align__(1024) float g_xn[MROWS * C];                // layernorm output (tf32)
__device__ __align__(1024) float g_qkv[(size_t)MROWS * 3 * C];   // [M, 3C] (tf32)
__device__ __align__(1024) float g_att[MROWS * C];               // attention out (tf32)
__device__ __align__(1024) float g_x1[MROWS * C];                // x + attn_proj
__device__ __align__(1024) float g_h[(size_t)MROWS * FF];        // FFN hidden (tf32)

// ---------------- helpers ----------------
__device__ __forceinline__ uint32_t smem_u32(const void* p) {
    uint32_t a;
    asm("{ .reg .u64 t; cvta.to.shared.u64 t, %1; cvt.u32.u64 %0, t; }" : "=r"(a) : "l"(p));
    return a;
}
__device__ __forceinline__ float to_tf32(float x) {
    float r; asm("cvt.rna.tf32.f32 %0, %1;" : "=f"(r) : "f"(x)); return r;
}

#define CP_ASYNC16(dst, src) \
    asm volatile("cp.async.cg.shared.global [%0], [%1], 16;" :: "r"(dst), "l"(src) : "memory")
#define CP_COMMIT() asm volatile("cp.async.commit_group;" ::: "memory")
#define CP_WAIT(n)  asm volatile("cp.async.wait_group %0;" :: "n"(n) : "memory")

__device__ __forceinline__ void mma_tf32(float* d, const uint32_t* a, const uint32_t* b) {
    asm volatile(
        "mma.sync.aligned.m16n8k8.row.col.f32.tf32.tf32.f32 "
        "{%0,%1,%2,%3}, {%4,%5,%6,%7}, {%8,%9}, {%0,%1,%2,%3};"
        : "+f"(d[0]), "+f"(d[1]), "+f"(d[2]), "+f"(d[3])
        : "r"(a[0]), "r"(a[1]), "r"(a[2]), "r"(a[3]), "r"(b[0]), "r"(b[1]));
}

// ---------------- tensor-core GEMM: C[M,N] = A[M,K] @ B[N,K]^T (both row-major, tf32) ----
// 128x128x32 tile, 8 warps (warp tile 64x32), 3-stage cp.async pipeline.
// EPI: 0 tf32-round (for qkv), 2 bias+gelu(+tf32 round), 3 bias+resid
#define PADK 36
#define STG 3
#define TILE_F (128 * PADK)
#define GEMM_SMEM (STG * 2 * TILE_F * 4)

template <int EPI>
__global__ __launch_bounds__(256, 1) void gemm_mma(
    const float* __restrict__ Ag, const float* __restrict__ Bg, float* __restrict__ Cm,
    int Kn, int Nn,
    const float* __restrict__ bias, const float* __restrict__ resid)
{
    extern __shared__ float sm[];
    float* smA = sm;
    float* smB = sm + STG * TILE_F;
    int tid = threadIdx.x, lane = tid & 31, wid = tid >> 5;
    int bx = blockIdx.x, by = blockIdx.y;
    int wm = (wid >> 2) * 64, wn = (wid & 3) * 32;

    const int NT = Kn >> 5;
    int crow = tid >> 3, ccol = (tid & 7) * 4;

    auto issue = [&](int s, int kt) {
        const float* As = Ag + ((size_t)(by * 128)) * Kn + kt * 32;
        const float* Bs = Bg + ((size_t)(bx * 128)) * Kn + kt * 32;
        uint32_t dA = smem_u32(smA + s * TILE_F);
        uint32_t dB = smem_u32(smB + s * TILE_F);
        #pragma unroll
        for (int i = 0; i < 4; i++) {
            int r = crow + i * 32;
            CP_ASYNC16(dA + (r * PADK + ccol) * 4, As + (size_t)r * Kn + ccol);
            CP_ASYNC16(dB + (r * PADK + ccol) * 4, Bs + (size_t)r * Kn + ccol);
        }
    };

    float acc[4][4][4];
    #pragma unroll
    for (int mi = 0; mi < 4; mi++)
        #pragma unroll
        for (int ni = 0; ni < 4; ni++)
            #pragma unroll
            for (int q = 0; q < 4; q++) acc[mi][ni][q] = 0.f;

    #pragma unroll
    for (int s = 0; s < STG - 1; s++) { issue(s, s); CP_COMMIT(); }

    int lq = lane >> 2, lr = lane & 3;

    for (int kt = 0; kt < NT; kt++) {
        int nx = kt + STG - 1;
        if (nx < NT) issue(nx % STG, nx);
        CP_COMMIT();
        CP_WAIT(STG - 2);
        __syncthreads();

        const float* At = smA + (kt % STG) * TILE_F;
        const float* Bt = smB + (kt % STG) * TILE_F;

        #pragma unroll
        for (int ks = 0; ks < 4; ks++) {
            int k0 = ks * 8;
            uint32_t a[4][4], b[4][2];
            #pragma unroll
            for (int mi = 0; mi < 4; mi++) {
                int r = wm + mi * 16 + lq;
                a[mi][0] = __float_as_uint(At[r * PADK + k0 + lr]);
                a[mi][1] = __float_as_uint(At[(r + 8) * PADK + k0 + lr]);
                a[mi][2] = __float_as_uint(At[r * PADK + k0 + lr + 4]);
                a[mi][3] = __float_as_uint(At[(r + 8) * PADK + k0 + lr + 4]);
            }
            #pragma unroll
            for (int ni = 0; ni < 4; ni++) {
                int n = wn + ni * 8 + lq;
                b[ni][0] = __float_as_uint(Bt[n * PADK + k0 + lr]);
                b[ni][1] = __float_as_uint(Bt[n * PADK + k0 + lr + 4]);
            }
            #pragma unroll
            for (int mi = 0; mi < 4; mi++)
                #pragma unroll
                for (int ni = 0; ni < 4; ni++)
                    mma_tf32(acc[mi][ni], a[mi], b[ni]);
        }
        __syncthreads();
    }

    #pragma unroll
    for (int ni = 0; ni < 4; ni++) {
        int c = bx * 128 + wn + ni * 8 + lr * 2;
        float b0 = 0.f, b1 = 0.f;
        if (EPI >= 1) { b0 = bias[c]; b1 = bias[c + 1]; }
        #pragma unroll
        for (int mi = 0; mi < 4; mi++) {
            int r0 = by * 128 + wm + mi * 16 + lq;
            #pragma unroll
            for (int half = 0; half < 2; half++) {
                int r = r0 + half * 8;
                float v0 = acc[mi][ni][half * 2 + 0] + b0;
                float v1 = acc[mi][ni][half * 2 + 1] + b1;
                if (EPI == 0) { v0 = to_tf32(v0); v1 = to_tf32(v1); }
                if (EPI == 2) {
                    v0 = to_tf32(0.5f * v0 * (1.0f + erff(v0 * 0.70710678118654752440f)));
                    v1 = to_tf32(0.5f * v1 * (1.0f + erff(v1 * 0.70710678118654752440f)));
                }
                if (EPI == 3) {
                    float2 rr = *(const float2*)(resid + (size_t)r * Nn + c);
                    v0 += rr.x; v1 += rr.y;
                }
                *(float2*)(Cm + (size_t)r * Nn + c) = make_float2(v0, v1);
            }
        }
    }
}

// ---------------- flash attention: fused scores/softmax/AV on mma.sync tf32 ----------------
// block = 256 thr (8 warps), grid (T/128, Bn*H). Warp w owns q rows [qt*128+w*16, +16).
// K/V tiles of 64 keys, cp.async double-buffered. P staged via warp-private SMEM rows.
#define QPAD 68
#define VPAD 72
#define KTILE_F (64 * QPAD)     // one K buffer
#define VTILE_F (64 * VPAD)
#define FLASH_SMEM ((128 * QPAD + 2 * KTILE_F + 2 * VTILE_F) * 4)

__global__ __launch_bounds__(256, 1) void flash_k(const float* __restrict__ qkv,
                                                  float* __restrict__ att) {
    extern __shared__ float sm[];
    float* Qs = sm;                            // [128][QPAD], reused as P buffer
    float* Ks = sm + 128 * QPAD;               // [2][64][QPAD]
    float* Vs = Ks + 2 * KTILE_F;              // [2][64][VPAD]

    int tid = threadIdx.x, lane = tid & 31, w = tid >> 5;
    int lq = lane >> 2, lr = lane & 3;
    int qt = blockIdx.x, bh = blockIdx.y;
    int b = bh >> 4, h = bh & 15;
    const int ktiles = 2 * qt + 2;

    // ---- async load helpers ----
    auto issueQ = [&]() {
        uint32_t dQ = smem_u32(Qs);
        #pragma unroll
        for (int i = 0; i < 8; i++) {
            int c = tid + i * 256;
            int row = c >> 4, col4 = (c & 15) * 4;
            const float* src = qkv + ((size_t)(b * T + qt * 128 + row)) * 3072 + h * 64 + col4;
            CP_ASYNC16(dQ + (row * QPAD + col4) * 4, src);
        }
    };
    auto issueKV = [&](int kt, int buf) {
        uint32_t dK = smem_u32(Ks + buf * KTILE_F);
        uint32_t dV = smem_u32(Vs + buf * VTILE_F);
        #pragma unroll
        for (int i = 0; i < 4; i++) {
            int c = tid + i * 256;
            int row = c >> 4, col4 = (c & 15) * 4;
            size_t gr = (size_t)(b * T + kt * 64 + row) * 3072 + h * 64 + col4;
            CP_ASYNC16(dK + (row * QPAD + col4) * 4, qkv + gr + 1024);
            CP_ASYNC16(dV + (row * VPAD + col4) * 4, qkv + gr + 2048);
        }
    };

    issueQ(); issueKV(0, 0); CP_COMMIT();
    issueKV(1, 1); CP_COMMIT();
    CP_WAIT(1);
    __syncthreads();   // Q + KV0 ready

    // ---- preload Q fragments (scale 1/8 folded in; exact on tf32 inputs) ----
    uint32_t qf[8][4];
    {
        int r0 = w * 16 + lq;
        #pragma unroll
        for (int ks = 0; ks < 8; ks++) {
            int k0 = ks * 8;
            qf[ks][0] = __float_as_uint(0.125f * Qs[r0 * QPAD + k0 + lr]);
            qf[ks][1] = __float_as_uint(0.125f * Qs[(r0 + 8) * QPAD + k0 + lr]);
            qf[ks][2] = __float_as_uint(0.125f * Qs[r0 * QPAD + k0 + lr + 4]);
            qf[ks][3] = __float_as_uint(0.125f * Qs[(r0 + 8) * QPAD + k0 + lr + 4]);
        }
    }
    __syncwarp();      // Qs region becomes warp-private P storage

    float oacc[8][4];
    #pragma unroll
    for (int ni = 0; ni < 8; ni++)
        #pragma unroll
        for (int q = 0; q < 4; q++) oacc[ni][q] = 0.f;
    float m0 = -1e30f, m1 = -1e30f, l0 = 0.f, l1 = 0.f;

    const int gr0 = qt * 128 + w * 16 + lq;   // global q row (thread's row A)
    const int gr1 = gr0 + 8;
    float* Pw = Qs;                            // P staging (warp-private rows)
    const int pr0 = (w * 16 + lq) * QPAD;
    const int pr1 = pr0 + 8 * QPAD;

    for (int kt = 0; kt < ktiles; kt++) {
        if (kt > 0) { CP_WAIT(1); __syncthreads(); }
        const float* K = Ks + (kt & 1) * KTILE_F;
        const float* V = Vs + (kt & 1) * VTILE_F;

        // ---- S = (Q/8) @ K^T : per-warp 16x64 ----
        float sacc[8][4];
        #pragma unroll
        for (int ni = 0; ni < 8; ni++)
            #pragma unroll
            for (int q = 0; q < 4; q++) sacc[ni][q] = 0.f;
        #pragma unroll
        for (int ks = 0; ks < 8; ks++) {
            int k0 = ks * 8;
            #pragma unroll
            for (int ni = 0; ni < 8; ni++) {
                uint32_t bf[2];
                int n = ni * 8 + lq;
                bf[0] = __float_as_uint(K[n * QPAD + k0 + lr]);
                bf[1] = __float_as_uint(K[n * QPAD + k0 + lr + 4]);
                mma_tf32(sacc[ni], qf[ks], bf);
            }
        }

        // ---- causal mask (only last two tiles can clip) ----
        if (kt >= 2 * qt) {
            #pragma unroll
            for (int ni = 0; ni < 8; ni++) {
                int cbase = kt * 64 + ni * 8 + lr * 2;
                #pragma unroll
                for (int j = 0; j < 2; j++) {
                    if (cbase + j > gr0) sacc[ni][j]     = -1e30f;
                    if (cbase + j > gr1) sacc[ni][2 + j] = -1e30f;
                }
            }
        }

        // ---- online softmax ----
        float mx0 = -1e30f, mx1 = -1e30f;
        #pragma unroll
        for (int ni = 0; ni < 8; ni++) {
            mx0 = fmaxf(mx0, fmaxf(sacc[ni][0], sacc[ni][1]));
            mx1 = fmaxf(mx1, fmaxf(sacc[ni][2], sacc[ni][3]));
        }
        #pragma unroll
        for (int off = 1; off <= 2; off <<= 1) {
            mx0 = fmaxf(mx0, __shfl_xor_sync(0xffffffffu, mx0, off));
            mx1 = fmaxf(mx1, __shfl_xor_sync(0xffffffffu, mx1, off));
        }
        float mn0 = fmaxf(m0, mx0), mn1 = fmaxf(m1, mx1);
        float al0 = __expf(m0 - mn0), al1 = __expf(m1 - mn1);
        m0 = mn0; m1 = mn1;
        float s0 = 0.f, s1 = 0.f;
        #pragma unroll
        for (int ni = 0; ni < 8; ni++) {
            sacc[ni][0] = __expf(sacc[ni][0] - mn0);
            sacc[ni][1] = __expf(sacc[ni][1] - mn0);
            sacc[ni][2] = __expf(sacc[ni][2] - mn1);
            sacc[ni][3] = __expf(sacc[ni][3] - mn1);
            s0 += sacc[ni][0] + sacc[ni][1];
            s1 += sacc[ni][2] + sacc[ni][3];
        }
        #pragma unroll
        for (int off = 1; off <= 2; off <<= 1) {
            s0 += __shfl_xor_sync(0xffffffffu, s0, off);
            s1 += __shfl_xor_sync(0xffffffffu, s1, off);
        }
        l0 = l0 * al0 + s0;
        l1 = l1 * al1 + s1;
        #pragma unroll
        for (int ni = 0; ni < 8; ni++) {
            oacc[ni][0] *= al0; oacc[ni][1] *= al0;
            oacc[ni][2] *= al1; oacc[ni][3] *= al1;
        }

        // ---- stage P (tf32) into warp-private SMEM rows ----
        #pragma unroll
        for (int ni = 0; ni < 8; ni++) {
            int cc = ni * 8 + lr * 2;
            *(float2*)&Pw[pr0 + cc] = make_float2(to_tf32(sacc[ni][0]), to_tf32(sacc[ni][1]));
            *(float2*)&Pw[pr1 + cc] = make_float2(to_tf32(sacc[ni][2]), to_tf32(sacc[ni][3]));
        }
        __syncwarp();

        // ---- O += P @ V ----
        #pragma unroll
        for (int ks = 0; ks < 8; ks++) {
            int k0 = ks * 8;
            uint32_t a[4];
            a[0] = __float_as_uint(Pw[pr0 + k0 + lr]);
            a[1] = __float_as_uint(Pw[pr1 + k0 + lr]);
            a[2] = __float_as_uint(Pw[pr0 + k0 + lr + 4]);
            a[3] = __float_as_uint(Pw[pr1 + k0 + lr + 4]);
            #pragma unroll
            for (int ni = 0; ni < 8; ni++) {
                uint32_t bf[2];
                int n = ni * 8 + lq;
                bf[0] = __float_as_uint(V[(k0 + lr) * VPAD + n]);
                bf[1] = __float_as_uint(V[(k0 + lr + 4) * VPAD + n]);
                mma_tf32(oacc[ni], a, bf);
            }
        }
        __syncwarp();

        __syncthreads();                   // all warps done with K/V buf before refill
        if (kt + 2 < ktiles) issueKV(kt + 2, kt & 1);
        CP_COMMIT();
    }

    // ---- finalize: O /= l, store (tf32) ----
    float inv0 = 1.0f / l0, inv1 = 1.0f / l1;
    size_t ro0 = ((size_t)(b * T) + gr0) * 1024 + h * 64;
    size_t ro1 = ((size_t)(b * T) + gr1) * 1024 + h * 64;
    #pragma unroll
    for (int ni = 0; ni < 8; ni++) {
        int cc = ni * 8 + lr * 2;
        *(float2*)(att + ro0 + cc) =
            make_float2(to_tf32(oacc[ni][0] * inv0), to_tf32(oacc[ni][1] * inv0));
        *(float2*)(att + ro1 + cc) =
            make_float2(to_tf32(oacc[ni][2] * inv1), to_tf32(oacc[ni][3] * inv1));
    }
}

// ---------------- layernorm: one block per row, tf32-rounded output ----------------
__global__ void layernorm_k(const float* __restrict__ x, const float* __restrict__ g,
                            const float* __restrict__ b, float* __restrict__ out) {
    int row = blockIdx.x;
    const float* xr = x + (size_t)row * C;
    float* yr = out + (size_t)row * C;
    float s = 0.f, s2 = 0.f;
    for (int i = threadIdx.x; i < C; i += blockDim.x) {
        float v = xr[i]; s += v; s2 += v * v;
    }
    __shared__ float sh[64];
    int lid = threadIdx.x & 31, wid = threadIdx.x >> 5;
    #pragma unroll
    for (int o = 16; o > 0; o >>= 1) {
        s  += __shfl_xor_sync(0xffffffffu, s,  o);
        s2 += __shfl_xor_sync(0xffffffffu, s2, o);
    }
    if (lid == 0) { sh[wid] = s; sh[wid + 32] = s2; }
    __syncthreads();
    if (threadIdx.x == 0) {
        float a = 0.f, a2 = 0.f;
        int nw = blockDim.x >> 5;
        for (int w = 0; w < nw; w++) { a += sh[w]; a2 += sh[w + 32]; }
        sh[0] = a; sh[1] = a2;
    }
    __syncthreads();
    float mean = sh[0] * (1.0f / C);
    float var  = sh[1] * (1.0f / C) - mean * mean;
    float rstd = rsqrtf(var + 1e-5f);
    for (int i = threadIdx.x; i < C; i += blockDim.x)
        yr[i] = to_tf32((xr[i] - mean) * rstd * g[i] + b[i]);
}

// ---------------- pack Wq/Wk/Wv [H,C,HD] -> g_wqkvT [3C, C] (tf32) ----------------
__global__ void pack_qkv_k(const float* __restrict__ Wq, const float* __restrict__ Wk,
                           const float* __restrict__ Wv) {
    int idx = blockIdx.x * blockDim.x + threadIdx.x;
    if (idx >= C * 3 * C) return;
    int k = idx % C;
    int n = idx / C;
    const float* W; int nn;
    if (n < C)          { W = Wq; nn = n; }
    else if (n < 2 * C) { W = Wk; nn = n - C; }
    else                { W = Wv; nn = n - 2 * C; }
    int h = nn >> 6, d = nn & 63;
    g_wqkvT[idx] = to_tf32(W[((size_t)h * C + k) * HD + d]);
}

// ---------------- tiled transpose src[K,N] -> dst[N,K] (tf32) ----------------
__global__ void transpose_tf32(const float* __restrict__ src, float* __restrict__ dst,
                               int Kn, int Nn) {
    __shared__ float tile[32][33];
    int k0 = blockIdx.y * 32, n0 = blockIdx.x * 32;
    int tx = threadIdx.x, ty = threadIdx.y;
    #pragma unroll
    for (int r = ty; r < 32; r += 8)
        tile[r][tx] = src[(size_t)(k0 + r) * Nn + n0 + tx];
    __syncthreads();
    #pragma unroll
    for (int r = ty; r < 32; r += 8)
        dst[(size_t)(n0 + r) * Kn + k0 + tx] = to_tf32(tile[tx][r]);
}

// ---------------- launch ----------------
extern "C" void kernel_launch(void* const* d_in, const int* in_sizes, int n_in,
                              void* d_out, int out_size) {
    const float* x      = (const float*)d_in[0];
    const float* ln1_g  = (const float*)d_in[1];
    const float* ln1_b  = (const float*)d_in[2];
    const float* ln2_g  = (const float*)d_in[3];
    const float* ln2_b  = (const float*)d_in[4];
    const float* Wq     = (const float*)d_in[5];
    const float* Wk     = (const float*)d_in[6];
    const float* Wv     = (const float*)d_in[7];
    const float* Wproj  = (const float*)d_in[8];
    const float* bproj  = (const float*)d_in[9];
    const float* W1     = (const float*)d_in[10];
    const float* b1     = (const float*)d_in[11];
    const float* W2     = (const float*)d_in[12];
    const float* b2     = (const float*)d_in[13];
    float* out = (float*)d_out;

    float *p_wqkvT, *p_wprojT, *p_w1T, *p_w2T, *p_xn, *p_qkv, *p_att, *p_x1, *p_h;
    cudaGetSymbolAddress((void**)&p_wqkvT,  g_wqkvT);
    cudaGetSymbolAddress((void**)&p_wprojT, g_wprojT);
    cudaGetSymbolAddress((void**)&p_w1T,    g_w1T);
    cudaGetSymbolAddress((void**)&p_w2T,    g_w2T);
    cudaGetSymbolAddress((void**)&p_xn,     g_xn);
    cudaGetSymbolAddress((void**)&p_qkv,    g_qkv);
    cudaGetSymbolAddress((void**)&p_att,    g_att);
    cudaGetSymbolAddress((void**)&p_x1,     g_x1);
    cudaGetSymbolAddress((void**)&p_h,      g_h);

    cudaFuncSetAttribute(gemm_mma<0>, cudaFuncAttributeMaxDynamicSharedMemorySize, GEMM_SMEM);
    cudaFuncSetAttribute(gemm_mma<2>, cudaFuncAttributeMaxDynamicSharedMemorySize, GEMM_SMEM);
    cudaFuncSetAttribute(gemm_mma<3>, cudaFuncAttributeMaxDynamicSharedMemorySize, GEMM_SMEM);
    cudaFuncSetAttribute(flash_k,     cudaFuncAttributeMaxDynamicSharedMemorySize, FLASH_SMEM);

    // 1) LN1 -> xn (tf32)
    layernorm_k<<<MROWS, 256>>>(x, ln1_g, ln1_b, p_xn);
    // 2) weight packs / transposes (tf32)
    pack_qkv_k<<<(C * 3 * C + 255) / 256, 256>>>(Wq, Wk, Wv);
    transpose_tf32<<<dim3(C / 32, C / 32),  dim3(32, 8)>>>(Wproj, p_wprojT, C, C);
    transpose_tf32<<<dim3(FF / 32, C / 32), dim3(32, 8)>>>(W1, p_w1T, C, FF);
    transpose_tf32<<<dim3(C / 32, FF / 32), dim3(32, 8)>>>(W2, p_w2T, FF, C);
    // 3) QKV GEMM (tensor): [4096,1024] @ [1024,3072], tf32-rounded output
    gemm_mma<0><<<dim3(3 * C / 128, MROWS / 128), 256, GEMM_SMEM>>>(
        p_xn, p_wqkvT, p_qkv, C, 3 * C, nullptr, nullptr);
    // 4) fused flash attention -> att (tf32)
    flash_k<<<dim3(T / 128, Bn * H), 256, FLASH_SMEM>>>(p_qkv, p_att);
    // 5) proj + bias + residual(x) -> x1
    gemm_mma<3><<<dim3(C / 128, MROWS / 128), 256, GEMM_SMEM>>>(
        p_att, p_wprojT, p_x1, C, C, bproj, x);
    // 6) LN2 -> xn (tf32)
    layernorm_k<<<MROWS, 256>>>(p_x1, ln2_g, ln2_b, p_xn);
    // 7) FFN1 + bias + gelu -> h (tf32)
    gemm_mma<2><<<dim3(FF / 128, MROWS / 128), 256, GEMM_SMEM>>>(
        p_xn, p_w1T, p_h, C, FF, b1, nullptr);
    // 8) FFN2 + bias + residual(x1) -> out
    gemm_mma<3><<<dim3(C / 128, MROWS / 128), 256, GEMM_SMEM>>>(
        p_h, p_w2T, out, FF, C, b2, p_x1);
}

// round 5
// speedup vs baseline: 5.0842x; 1.6167x over previous
#include <cuda_runtime.h>
#include <cuda_fp16.h>
#include <math.h>
#include <stdint.h>

#define Bn 4
#define T 1024
#define C 1024
#define H 16
#define HD 64
#define FF 4096
#define MROWS (Bn*T)   // 4096

// ---------------- scratch (device globals; no runtime allocation) ----------------
__device__ __align__(1024) __half g_wqkvT[3*C * C];               // [3072,1024] W_qkv^T
__device__ __align__(1024) __half g_wprojT[C * C];                // [1024,1024] Wproj^T
__device__ __align__(1024) __half g_w1T[FF * C];                  // [4096,1024] W1^T
__device__ __align__(1024) __half g_w2T[C * FF];                  // [1024,4096] W2^T
__device__ __align__(1024) __half g_xn[MROWS * C];                // layernorm out
__device__ __align__(1024) __half g_qkv[(size_t)MROWS * 3 * C];   // [M, 3C]
__device__ __align__(1024) __half g_att[MROWS * C];               // attention out
__device__ __align__(1024) __half g_h[(size_t)MROWS * FF];        // FFN hidden
__device__ __align__(1024) float  g_x1[MROWS * C];                // x + attn_proj (fp32)

// ---------------- helpers ----------------
__device__ __forceinline__ uint32_t smem_u32(const void* p) {
    uint32_t a;
    asm("{ .reg .u64 t; cvta.to.shared.u64 t, %1; cvt.u32.u64 %0, t; }" : "=r"(a) : "l"(p));
    return a;
}

#define CP_ASYNC16(dst, src) \
    asm volatile("cp.async.cg.shared.global [%0], [%1], 16;" :: "r"(dst), "l"(src) : "memory")
#define CP_COMMIT() asm volatile("cp.async.commit_group;" ::: "memory")
#define CP_WAIT(n)  asm volatile("cp.async.wait_group %0;" :: "n"(n) : "memory")

#define LDSM4(r0, r1, r2, r3, addr) \
    asm volatile("ldmatrix.sync.aligned.m8n8.x4.shared.b16 {%0,%1,%2,%3}, [%4];" \
        : "=r"(r0), "=r"(r1), "=r"(r2), "=r"(r3) : "r"(addr))
#define LDSM4T(r0, r1, r2, r3, addr) \
    asm volatile("ldmatrix.sync.aligned.m8n8.x4.trans.shared.b16 {%0,%1,%2,%3}, [%4];" \
        : "=r"(r0), "=r"(r1), "=r"(r2), "=r"(r3) : "r"(addr))

__device__ __forceinline__ void mma_f16(float* d, const uint32_t* a, const uint32_t* b) {
    asm volatile(
        "mma.sync.aligned.m16n8k16.row.col.f32.f16.f16.f32 "
        "{%0,%1,%2,%3}, {%4,%5,%6,%7}, {%8,%9}, {%0,%1,%2,%3};"
        : "+f"(d[0]), "+f"(d[1]), "+f"(d[2]), "+f"(d[3])
        : "r"(a[0]), "r"(a[1]), "r"(a[2]), "r"(a[3]), "r"(b[0]), "r"(b[1]));
}
__device__ __forceinline__ uint32_t hmul2u(uint32_t a, uint32_t b) {
    __half2 r = __hmul2(*(__half2*)&a, *(__half2*)&b);
    return *(uint32_t*)&r;
}
__device__ __forceinline__ uint32_t f22h(float x, float y) {
    __half2 h = __floats2half2_rn(x, y);
    return *(uint32_t*)&h;
}

// ---------------- fp16 tensor-core GEMM: C[M,N] = A[M,K] @ B[N,K]^T ----------------
// 128x128x32 tile (32 halfs per k-tile = 2 k16 steps), 8 warps (warp 64x32), 3-stage cp.async.
// EPI: 0 -> half out; 2 bias+gelu -> half out; 3 bias+resid(fp32) -> float out
#define PADH 40
#define STG 3
#define TILE_H (128 * PADH)
#define GEMM_SMEM (STG * 2 * TILE_H * 2)

template <int EPI>
__global__ __launch_bounds__(256, 1) void gemm_h(
    const __half* __restrict__ Ag, const __half* __restrict__ Bg, void* __restrict__ Cm,
    int Kn, int Nn,
    const float* __restrict__ bias, const float* __restrict__ resid)
{
    extern __shared__ __half smh[];
    __half* smA = smh;
    __half* smB = smh + STG * TILE_H;
    int tid = threadIdx.x, lane = tid & 31, wid = tid >> 5;
    int bx = blockIdx.x, by = blockIdx.y;
    int wm = (wid >> 2) * 64, wn = (wid & 3) * 32;
    int lane16 = lane & 15, lanehi = lane >> 4;
    int lq = lane >> 2, lr = lane & 3;

    const int NT = Kn >> 5;
    int crow = tid >> 2, ccol = (tid & 3) * 8;   // 512 chunks: 2 per thread

    auto issue = [&](int s, int kt) {
        const __half* As = Ag + (size_t)(by * 128) * Kn + kt * 32;
        const __half* Bs = Bg + (size_t)(bx * 128) * Kn + kt * 32;
        uint32_t dA = smem_u32(smA + s * TILE_H);
        uint32_t dB = smem_u32(smB + s * TILE_H);
        #pragma unroll
        for (int i = 0; i < 2; i++) {
            int r = crow + i * 64;
            CP_ASYNC16(dA + (r * PADH + ccol) * 2, As + (size_t)r * Kn + ccol);
            CP_ASYNC16(dB + (r * PADH + ccol) * 2, Bs + (size_t)r * Kn + ccol);
        }
    };

    float acc[4][4][4];
    #pragma unroll
    for (int mi = 0; mi < 4; mi++)
        #pragma unroll
        for (int ni = 0; ni < 4; ni++)
            #pragma unroll
            for (int q = 0; q < 4; q++) acc[mi][ni][q] = 0.f;

    #pragma unroll
    for (int s = 0; s < STG - 1; s++) { issue(s, s); CP_COMMIT(); }

    for (int kt = 0; kt < NT; kt++) {
        int nx = kt + STG - 1;
        if (nx < NT) issue(nx % STG, nx);
        CP_COMMIT();
        CP_WAIT(STG - 2);
        __syncthreads();

        const __half* At = smA + (kt % STG) * TILE_H;
        const __half* Bt = smB + (kt % STG) * TILE_H;

        #pragma unroll
        for (int ks = 0; ks < 2; ks++) {
            int k0 = ks * 16;
            uint32_t a[4][4], b[4][2];
            #pragma unroll
            for (int mi = 0; mi < 4; mi++) {
                uint32_t ad = smem_u32(At + (wm + mi * 16 + lane16) * PADH + k0 + lanehi * 8);
                LDSM4(a[mi][0], a[mi][1], a[mi][2], a[mi][3], ad);
            }
            #pragma unroll
            for (int nb = 0; nb < 2; nb++) {
                uint32_t m0, m1, m2, m3;
                uint32_t ad = smem_u32(Bt + (wn + nb * 16 + lane16) * PADH + k0 + lanehi * 8);
                LDSM4(m0, m1, m2, m3, ad);
                b[2 * nb][0] = m0; b[2 * nb][1] = m2;
                b[2 * nb + 1][0] = m1; b[2 * nb + 1][1] = m3;
            }
            #pragma unroll
            for (int mi = 0; mi < 4; mi++)
                #pragma unroll
                for (int ni = 0; ni < 4; ni++)
                    mma_f16(acc[mi][ni], a[mi], b[ni]);
        }
        __syncthreads();
    }

    #pragma unroll
    for (int ni = 0; ni < 4; ni++) {
        int c = bx * 128 + wn + ni * 8 + lr * 2;
        float b0 = 0.f, b1 = 0.f;
        if (EPI >= 1) { b0 = bias[c]; b1 = bias[c + 1]; }
        #pragma unroll
        for (int mi = 0; mi < 4; mi++) {
            int r0 = by * 128 + wm + mi * 16 + lq;
            #pragma unroll
            for (int half_ = 0; half_ < 2; half_++) {
                int r = r0 + half_ * 8;
                float v0 = acc[mi][ni][half_ * 2 + 0] + b0;
                float v1 = acc[mi][ni][half_ * 2 + 1] + b1;
                if (EPI == 2) {
                    v0 = 0.5f * v0 * (1.0f + erff(v0 * 0.70710678118654752440f));
                    v1 = 0.5f * v1 * (1.0f + erff(v1 * 0.70710678118654752440f));
                }
                if (EPI == 3) {
                    float2 rr = *(const float2*)(resid + (size_t)r * Nn + c);
                    *(float2*)((float*)Cm + (size_t)r * Nn + c) = make_float2(v0 + rr.x, v1 + rr.y);
                } else {
                    *(__half2*)((__half*)Cm + (size_t)r * Nn + c) = __floats2half2_rn(v0, v1);
                }
            }
        }
    }
}

// ---------------- fp16 flash attention ----------------
// block 256 (8 warps), grid (T/128, Bn*H). Warp w: q rows [qt*128+w*16, +16).
// K/V tiles of 64 keys double-buffered. P stays in registers (C-frag -> A-frag repack).
#define FQP 72
#define FKT (64 * FQP)
#define FLASH_SMEM ((128 * FQP + 2 * FKT + 2 * FKT) * 2)

__global__ __launch_bounds__(256, 1) void flash_h(const __half* __restrict__ qkv,
                                                  __half* __restrict__ att) {
    extern __shared__ __half smh[];
    __half* Qs = smh;                 // [128][FQP]
    __half* Ks = smh + 128 * FQP;     // [2][64][FQP]
    __half* Vs = Ks + 2 * FKT;        // [2][64][FQP]

    int tid = threadIdx.x, lane = tid & 31, w = tid >> 5;
    int lane16 = lane & 15, lanehi = lane >> 4;
    int lq = lane >> 2, lr = lane & 3;
    int qt = blockIdx.x, bh = blockIdx.y;
    int b = bh >> 4, h = bh & 15;
    const int ktiles = 2 * qt + 2;

    auto issueQ = [&]() {
        uint32_t dQ = smem_u32(Qs);
        #pragma unroll
        for (int i = 0; i < 4; i++) {
            int c = tid + i * 256;
            int row = c >> 3, col = (c & 7) * 8;
            const __half* src = qkv + (size_t)(b * T + qt * 128 + row) * 3072 + h * 64 + col;
            CP_ASYNC16(dQ + (row * FQP + col) * 2, src);
        }
    };
    auto issueKV = [&](int kt, int buf) {
        uint32_t dK = smem_u32(Ks + buf * FKT);
        uint32_t dV = smem_u32(Vs + buf * FKT);
        #pragma unroll
        for (int i = 0; i < 2; i++) {
            int c = tid + i * 256;
            int row = c >> 3, col = (c & 7) * 8;
            size_t gr = (size_t)(b * T + kt * 64 + row) * 3072 + h * 64 + col;
            CP_ASYNC16(dK + (row * FQP + col) * 2, qkv + gr + 1024);
            CP_ASYNC16(dV + (row * FQP + col) * 2, qkv + gr + 2048);
        }
    };

    issueQ(); issueKV(0, 0); CP_COMMIT();
    issueKV(1, 1); CP_COMMIT();
    CP_WAIT(1);
    __syncthreads();

    // Q fragments, scale 1/8 folded (exact power of two)
    uint32_t qf[4][4];
    {
        __half2 s8 = __float2half2_rn(0.125f);
        uint32_t s8u = *(uint32_t*)&s8;
        #pragma unroll
        for (int ks = 0; ks < 4; ks++) {
            uint32_t ad = smem_u32(Qs + (w * 16 + lane16) * FQP + ks * 16 + lanehi * 8);
            LDSM4(qf[ks][0], qf[ks][1], qf[ks][2], qf[ks][3], ad);
            #pragma unroll
            for (int j = 0; j < 4; j++) qf[ks][j] = hmul2u(qf[ks][j], s8u);
        }
    }

    float oacc[8][4];
    #pragma unroll
    for (int ni = 0; ni < 8; ni++)
        #pragma unroll
        for (int q = 0; q < 4; q++) oacc[ni][q] = 0.f;
    float m0 = -1e30f, m1 = -1e30f, l0 = 0.f, l1 = 0.f;

    const int gr0 = qt * 128 + w * 16 + lq;
    const int gr1 = gr0 + 8;

    for (int kt = 0; kt < ktiles; kt++) {
        if (kt > 0) { CP_WAIT(1); __syncthreads(); }
        const __half* K = Ks + (kt & 1) * FKT;
        const __half* V = Vs + (kt & 1) * FKT;

        // ---- S = (Q/8) @ K^T : warp 16x64 ----
        float sacc[8][4];
        #pragma unroll
        for (int ni = 0; ni < 8; ni++)
            #pragma unroll
            for (int q = 0; q < 4; q++) sacc[ni][q] = 0.f;
        #pragma unroll
        for (int ks = 0; ks < 4; ks++) {
            int k0 = ks * 16;
            #pragma unroll
            for (int nb = 0; nb < 4; nb++) {
                uint32_t m0r, m1r, m2r, m3r;
                uint32_t ad = smem_u32(K + (nb * 16 + lane16) * FQP + k0 + lanehi * 8);
                LDSM4(m0r, m1r, m2r, m3r, ad);
                uint32_t blo[2] = {m0r, m2r}, bhi[2] = {m1r, m3r};
                mma_f16(sacc[2 * nb], qf[ks], blo);
                mma_f16(sacc[2 * nb + 1], qf[ks], bhi);
            }
        }

        // ---- causal mask ----
        if (kt >= 2 * qt) {
            #pragma unroll
            for (int ni = 0; ni < 8; ni++) {
                int cbase = kt * 64 + ni * 8 + lr * 2;
                #pragma unroll
                for (int j = 0; j < 2; j++) {
                    if (cbase + j > gr0) sacc[ni][j]     = -1e30f;
                    if (cbase + j > gr1) sacc[ni][2 + j] = -1e30f;
                }
            }
        }

        // ---- online softmax ----
        float mx0 = -1e30f, mx1 = -1e30f;
        #pragma unroll
        for (int ni = 0; ni < 8; ni++) {
            mx0 = fmaxf(mx0, fmaxf(sacc[ni][0], sacc[ni][1]));
            mx1 = fmaxf(mx1, fmaxf(sacc[ni][2], sacc[ni][3]));
        }
        #pragma unroll
        for (int off = 1; off <= 2; off <<= 1) {
            mx0 = fmaxf(mx0, __shfl_xor_sync(0xffffffffu, mx0, off));
            mx1 = fmaxf(mx1, __shfl_xor_sync(0xffffffffu, mx1, off));
        }
        float mn0 = fmaxf(m0, mx0), mn1 = fmaxf(m1, mx1);
        float al0 = __expf(m0 - mn0), al1 = __expf(m1 - mn1);
        m0 = mn0; m1 = mn1;
        float s0 = 0.f, s1 = 0.f;
        #pragma unroll
        for (int ni = 0; ni < 8; ni++) {
            sacc[ni][0] = __expf(sacc[ni][0] - mn0);
            sacc[ni][1] = __expf(sacc[ni][1] - mn0);
            sacc[ni][2] = __expf(sacc[ni][2] - mn1);
            sacc[ni][3] = __expf(sacc[ni][3] - mn1);
            s0 += sacc[ni][0] + sacc[ni][1];
            s1 += sacc[ni][2] + sacc[ni][3];
        }
        #pragma unroll
        for (int off = 1; off <= 2; off <<= 1) {
            s0 += __shfl_xor_sync(0xffffffffu, s0, off);
            s1 += __shfl_xor_sync(0xffffffffu, s1, off);
        }
        l0 = l0 * al0 + s0;
        l1 = l1 * al1 + s1;
        #pragma unroll
        for (int ni = 0; ni < 8; ni++) {
            oacc[ni][0] *= al0; oacc[ni][1] *= al0;
            oacc[ni][2] *= al1; oacc[ni][3] *= al1;
        }

        // ---- O += P @ V : P repacked in registers (C-frag -> A-frag) ----
        #pragma unroll
        for (int kk = 0; kk < 4; kk++) {
            uint32_t a[4];
            a[0] = f22h(sacc[2 * kk][0], sacc[2 * kk][1]);
            a[1] = f22h(sacc[2 * kk][2], sacc[2 * kk][3]);
            a[2] = f22h(sacc[2 * kk + 1][0], sacc[2 * kk + 1][1]);
            a[3] = f22h(sacc[2 * kk + 1][2], sacc[2 * kk + 1][3]);
            #pragma unroll
            for (int dbp = 0; dbp < 4; dbp++) {
                uint32_t m0r, m1r, m2r, m3r;
                uint32_t ad = smem_u32(V + (kk * 16 + lane16) * FQP + dbp * 16 + lanehi * 8);
                LDSM4T(m0r, m1r, m2r, m3r, ad);
                uint32_t blo[2] = {m0r, m1r}, bhi[2] = {m2r, m3r};
                mma_f16(oacc[2 * dbp], a, blo);
                mma_f16(oacc[2 * dbp + 1], a, bhi);
            }
        }

        __syncthreads();
        if (kt + 2 < ktiles) issueKV(kt + 2, kt & 1);
        CP_COMMIT();
    }

    float inv0 = 1.0f / l0, inv1 = 1.0f / l1;
    size_t ro0 = ((size_t)(b * T) + gr0) * 1024 + h * 64;
    size_t ro1 = ((size_t)(b * T) + gr1) * 1024 + h * 64;
    #pragma unroll
    for (int ni = 0; ni < 8; ni++) {
        int cc = ni * 8 + lr * 2;
        *(__half2*)(att + ro0 + cc) = __floats2half2_rn(oacc[ni][0] * inv0, oacc[ni][1] * inv0);
        *(__half2*)(att + ro1 + cc) = __floats2half2_rn(oacc[ni][2] * inv1, oacc[ni][3] * inv1);
    }
}

// ---------------- layernorm: one block per row, half output ----------------
__global__ void layernorm_k(const float* __restrict__ x, const float* __restrict__ g,
                            const float* __restrict__ b, __half* __restrict__ out) {
    int row = blockIdx.x;
    const float* xr = x + (size_t)row * C;
    __half* yr = out + (size_t)row * C;
    float s = 0.f, s2 = 0.f;
    for (int i = threadIdx.x; i < C; i += blockDim.x) {
        float v = xr[i]; s += v; s2 += v * v;
    }
    __shared__ float sh[64];
    int lid = threadIdx.x & 31, wid = threadIdx.x >> 5;
    #pragma unroll
    for (int o = 16; o > 0; o >>= 1) {
        s  += __shfl_xor_sync(0xffffffffu, s,  o);
        s2 += __shfl_xor_sync(0xffffffffu, s2, o);
    }
    if (lid == 0) { sh[wid] = s; sh[wid + 32] = s2; }
    __syncthreads();
    if (threadIdx.x == 0) {
        float a = 0.f, a2 = 0.f;
        int nw = blockDim.x >> 5;
        for (int w = 0; w < nw; w++) { a += sh[w]; a2 += sh[w + 32]; }
        sh[0] = a; sh[1] = a2;
    }
    __syncthreads();
    float mean = sh[0] * (1.0f / C);
    float var  = sh[1] * (1.0f / C) - mean * mean;
    float rstd = rsqrtf(var + 1e-5f);
    for (int i = threadIdx.x; i < C; i += blockDim.x)
        yr[i] = __float2half_rn((xr[i] - mean) * rstd * g[i] + b[i]);
}

// ---------------- pack Wq/Wk/Wv [H,C,HD] -> g_wqkvT [3C, C] (half) ----------------
__global__ void pack_qkv_k(const float* __restrict__ Wq, const float* __restrict__ Wk,
                           const float* __restrict__ Wv) {
    int idx = blockIdx.x * blockDim.x + threadIdx.x;
    if (idx >= C * 3 * C) return;
    int k = idx % C;
    int n = idx / C;
    const float* W; int nn;
    if (n < C)          { W = Wq; nn = n; }
    else if (n < 2 * C) { W = Wk; nn = n - C; }
    else                { W = Wv; nn = n - 2 * C; }
    int h = nn >> 6, d = nn & 63;
    g_wqkvT[idx] = __float2half_rn(W[((size_t)h * C + k) * HD + d]);
}

// ---------------- tiled transpose src[K,N] -> dst[N,K] (half) ----------------
__global__ void transpose_h(const float* __restrict__ src, __half* __restrict__ dst,
                            int Kn, int Nn) {
    __shared__ float tile[32][33];
    int k0 = blockIdx.y * 32, n0 = blockIdx.x * 32;
    int tx = threadIdx.x, ty = threadIdx.y;
    #pragma unroll
    for (int r = ty; r < 32; r += 8)
        tile[r][tx] = src[(size_t)(k0 + r) * Nn + n0 + tx];
    __syncthreads();
    #pragma unroll
    for (int r = ty; r < 32; r += 8)
        dst[(size_t)(n0 + r) * Kn + k0 + tx] = __float2half_rn(tile[tx][r]);
}

// ---------------- launch ----------------
extern "C" void kernel_launch(void* const* d_in, const int* in_sizes, int n_in,
                              void* d_out, int out_size) {
    const float* x      = (const float*)d_in[0];
    const float* ln1_g  = (const float*)d_in[1];
    const float* ln1_b  = (const float*)d_in[2];
    const float* ln2_g  = (const float*)d_in[3];
    const float* ln2_b  = (const float*)d_in[4];
    const float* Wq     = (const float*)d_in[5];
    const float* Wk     = (const float*)d_in[6];
    const float* Wv     = (const float*)d_in[7];
    const float* Wproj  = (const float*)d_in[8];
    const float* bproj  = (const float*)d_in[9];
    const float* W1     = (const float*)d_in[10];
    const float* b1     = (const float*)d_in[11];
    const float* W2     = (const float*)d_in[12];
    const float* b2     = (const float*)d_in[13];
    float* out = (float*)d_out;

    __half *p_wqkvT, *p_wprojT, *p_w1T, *p_w2T, *p_xn, *p_qkv, *p_att, *p_h;
    float* p_x1;
    cudaGetSymbolAddress((void**)&p_wqkvT,  g_wqkvT);
    cudaGetSymbolAddress((void**)&p_wprojT, g_wprojT);
    cudaGetSymbolAddress((void**)&p_w1T,    g_w1T);
    cudaGetSymbolAddress((void**)&p_w2T,    g_w2T);
    cudaGetSymbolAddress((void**)&p_xn,     g_xn);
    cudaGetSymbolAddress((void**)&p_qkv,    g_qkv);
    cudaGetSymbolAddress((void**)&p_att,    g_att);
    cudaGetSymbolAddress((void**)&p_x1,     g_x1);
    cudaGetSymbolAddress((void**)&p_h,      g_h);

    cudaFuncSetAttribute(gemm_h<0>, cudaFuncAttributeMaxDynamicSharedMemorySize, GEMM_SMEM);
    cudaFuncSetAttribute(gemm_h<2>, cudaFuncAttributeMaxDynamicSharedMemorySize, GEMM_SMEM);
    cudaFuncSetAttribute(gemm_h<3>, cudaFuncAttributeMaxDynamicSharedMemorySize, GEMM_SMEM);
    cudaFuncSetAttribute(flash_h,   cudaFuncAttributeMaxDynamicSharedMemorySize, FLASH_SMEM);

    // 1) LN1 -> xn (half)
    layernorm_k<<<MROWS, 256>>>(x, ln1_g, ln1_b, p_xn);
    // 2) weight packs / transposes (half)
    pack_qkv_k<<<(C * 3 * C + 255) / 256, 256>>>(Wq, Wk, Wv);
    transpose_h<<<dim3(C / 32, C / 32),  dim3(32, 8)>>>(Wproj, p_wprojT, C, C);
    transpose_h<<<dim3(FF / 32, C / 32), dim3(32, 8)>>>(W1, p_w1T, C, FF);
    transpose_h<<<dim3(C / 32, FF / 32), dim3(32, 8)>>>(W2, p_w2T, FF, C);
    // 3) QKV GEMM: [4096,1024] @ [1024,3072] -> half
    gemm_h<0><<<dim3(3 * C / 128, MROWS / 128), 256, GEMM_SMEM>>>(
        p_xn, p_wqkvT, p_qkv, C, 3 * C, nullptr, nullptr);
    // 4) fused flash attention -> att (half)
    flash_h<<<dim3(T / 128, Bn * H), 256, FLASH_SMEM>>>(p_qkv, p_att);
    // 5) proj + bias + residual(x) -> x1 (fp32)
    gemm_h<3><<<dim3(C / 128, MROWS / 128), 256, GEMM_SMEM>>>(
        p_att, p_wprojT, p_x1, C, C, bproj, x);
    // 6) LN2 -> xn (half)
    layernorm_k<<<MROWS, 256>>>(p_x1, ln2_g, ln2_b, p_xn);
    // 7) FFN1 + bias + gelu -> h (half)
    gemm_h<2><<<dim3(FF / 128, MROWS / 128), 256, GEMM_SMEM>>>(
        p_xn, p_w1T, p_h, C, FF, b1, nullptr);
    // 8) FFN2 + bias + residual(x1) -> out (fp32)
    gemm_h<3><<<dim3(C / 128, MROWS / 128), 256, GEMM_SMEM>>>(
        p_h, p_w2T, out, FF, C, b2, p_x1);
}